// round 1
// baseline (speedup 1.0000x reference)
#include <cuda_runtime.h>
#include <math.h>

// ---------------- problem constants ----------------
#define NTOK  4096            // B*L
#define LSEQ  1024
#define BATCH 4
#define DM    1024
#define DI    2048
#define DS    16
#define DTR   64
#define XPD   96              // DTR + 2*DS
#define NEXP  8
#define HEXP  1024

// ---------------- device scratch (no allocations allowed) ----------------
__device__ float g_x [NTOK*DM];        // residual stream
__device__ float g_uz[NTOK*2*DI];      // in_proj output (u|z)
__device__ float g_u [NTOK*DI];        // conv+silu(u)
__device__ float g_xp[NTOK*XPD];       // x_proj output (dt_raw|B|C)
__device__ float g_dt[NTOK*DI];        // softplus(dt)
__device__ float g_y [NTOK*DI];        // ssm out * silu(z)
__device__ float g_t [NTOK*DM];        // mamba-out / moe-out (pre-LN)
__device__ float g_h [NTOK*HEXP];      // moe hidden
__device__ float g_mask[NTOK];
__device__ float g_pooled[BATCH*DM];
__device__ int   g_eidx[NTOK];
__device__ float g_ew  [NTOK];
__device__ int   g_perm[NTOK];
__device__ int   g_cnt[NEXP], g_off[NEXP], g_fill[NEXP], g_cntb[BATCH];

// ---------------- embed ----------------
__global__ void embed_k(const int* __restrict__ tok, const float* __restrict__ emb,
                        const float* __restrict__ pos) {
    int i = blockIdx.x * blockDim.x + threadIdx.x;      // over NTOK*DM
    int t = i / DM, d = i % DM;
    int l = t % LSEQ;
    g_x[i] = emb[(size_t)tok[t] * DM + d] + pos[l * DM + d];
}

// ---------------- generic SGEMM: C[M,N] = act(A[M,K] @ W[N,K]^T + bias) ----------------
// mode 0: dense. mode 1: gather A rows via perm (MoE gemm1), C stored at base+m.
// mode 2: A contiguous at base (MoE gemm2), C scattered via perm with rowscale.
__global__ __launch_bounds__(256) void gemm_tn(
    const float* __restrict__ A, int lda,
    const float* __restrict__ W, int ldw, size_t w_zstride,
    float* __restrict__ C, int ldc,
    const float* __restrict__ bias, int bias_zstride,
    int M_fixed, const int* __restrict__ cntp, const int* __restrict__ offp,
    const int* __restrict__ perm, const float* __restrict__ rowscale,
    int mode, int N, int K, int act)
{
    int e = blockIdx.z;
    int M = cntp ? cntp[e] : M_fixed;
    int base = offp ? offp[e] : 0;
    int m0 = blockIdx.x * 128;
    if (m0 >= M) return;
    int n0 = blockIdx.y * 128;

    const float* Wz = W + (size_t)e * w_zstride;

    __shared__ float As[8][128];
    __shared__ float Bs[8][128];

    int tid = threadIdx.x;
    int rowL = tid >> 1;                 // 0..127
    int kOff = (tid & 1) * 4;

    // A tile source row
    int am = m0 + rowL;
    bool avalid = am < M;
    long arow;
    if (mode == 1)      arow = avalid ? (long)perm[base + am] : 0;
    else if (mode == 2) arow = base + am;
    else                arow = am;
    const float* Aptr = A + (size_t)arow * lda;

    // W tile source row
    int wn = n0 + rowL;
    bool wvalid = wn < N;
    const float* Wptr = Wz + (size_t)(wvalid ? wn : 0) * ldw;

    float acc[8][8];
#pragma unroll
    for (int i = 0; i < 8; i++)
#pragma unroll
        for (int j = 0; j < 8; j++) acc[i][j] = 0.f;

    int tm = (tid >> 4) * 8;
    int tn = (tid & 15) * 8;

    for (int k0 = 0; k0 < K; k0 += 8) {
        float4 av = avalid ? *(const float4*)(Aptr + k0 + kOff) : make_float4(0, 0, 0, 0);
        float4 wv = wvalid ? *(const float4*)(Wptr + k0 + kOff) : make_float4(0, 0, 0, 0);
        __syncthreads();
        As[kOff + 0][rowL] = av.x; As[kOff + 1][rowL] = av.y;
        As[kOff + 2][rowL] = av.z; As[kOff + 3][rowL] = av.w;
        Bs[kOff + 0][rowL] = wv.x; Bs[kOff + 1][rowL] = wv.y;
        Bs[kOff + 2][rowL] = wv.z; Bs[kOff + 3][rowL] = wv.w;
        __syncthreads();
#pragma unroll
        for (int kk = 0; kk < 8; kk++) {
            float4 a0 = *(const float4*)&As[kk][tm];
            float4 a1 = *(const float4*)&As[kk][tm + 4];
            float4 b0 = *(const float4*)&Bs[kk][tn];
            float4 b1 = *(const float4*)&Bs[kk][tn + 4];
            float a[8] = {a0.x, a0.y, a0.z, a0.w, a1.x, a1.y, a1.z, a1.w};
            float b[8] = {b0.x, b0.y, b0.z, b0.w, b1.x, b1.y, b1.z, b1.w};
#pragma unroll
            for (int i = 0; i < 8; i++)
#pragma unroll
                for (int j = 0; j < 8; j++) acc[i][j] += a[i] * b[j];
        }
    }

#pragma unroll
    for (int i = 0; i < 8; i++) {
        int m = m0 + tm + i;
        if (m >= M) continue;
        long crow; float scale = 1.f;
        if (mode == 2)      { crow = perm[base + m]; scale = rowscale[crow]; }
        else if (mode == 1) { crow = base + m; }
        else                { crow = m; }
        float* Crow = C + (size_t)crow * ldc;
#pragma unroll
        for (int j = 0; j < 8; j++) {
            int n = n0 + tn + j;
            if (n >= N) continue;
            float v = acc[i][j];
            if (bias) v += bias[(size_t)e * bias_zstride + n];
            if (act == 1) v = fmaxf(v, 0.f);
            else if (act == 2) v = (v > 20.f) ? v : log1pf(expf(v));  // softplus
            Crow[n] = v * scale;
        }
    }
}

// ---------------- causal depthwise conv (DC=4) + silu ----------------
__global__ void conv_silu_k(const float* __restrict__ cw, const float* __restrict__ cb) {
    int i = blockIdx.x * 256 + threadIdx.x;
    if (i >= NTOK * DI) return;
    int t = i / DI, d = i % DI;
    int b = t / LSEQ, l = t % LSEQ;
    float acc = cb[d];
#pragma unroll
    for (int k = 0; k < 4; k++) {
        int ll = l - 3 + k;
        if (ll >= 0) acc += g_uz[(size_t)(b * LSEQ + ll) * (2 * DI) + d] * cw[d * 4 + k];
    }
    g_u[i] = acc / (1.f + __expf(-acc));   // silu
}

// ---------------- selective-scan (sequential over L) ----------------
__global__ __launch_bounds__(256) void ssm_scan_k(const float* __restrict__ A_log,
                                                  const float* __restrict__ Dp) {
    int b = blockIdx.x;
    int d = blockIdx.y * 256 + threadIdx.x;
    float A[DS];
#pragma unroll
    for (int n = 0; n < DS; n++) A[n] = -expf(A_log[d * DS + n]);
    float Dv = Dp[d];
    float h[DS];
#pragma unroll
    for (int n = 0; n < DS; n++) h[n] = 0.f;

    __shared__ float Bs[64][DS], Cs[64][DS];

    for (int c = 0; c < LSEQ / 64; c++) {
        __syncthreads();
        for (int i = threadIdx.x; i < 64 * DS; i += 256) {
            int s = i / DS, n = i % DS;
            int tok = b * LSEQ + c * 64 + s;
            Bs[s][n] = g_xp[tok * XPD + DTR + n];
            Cs[s][n] = g_xp[tok * XPD + DTR + DS + n];
        }
        __syncthreads();
        for (int s = 0; s < 64; s++) {
            int tok = b * LSEQ + c * 64 + s;
            float ut  = g_u [(size_t)tok * DI + d];
            float dtt = g_dt[(size_t)tok * DI + d];
            float du = dtt * ut;
            float yv = 0.f;
#pragma unroll
            for (int n = 0; n < DS; n++) {
                h[n] = __expf(dtt * A[n]) * h[n] + du * Bs[s][n];
                yv += h[n] * Cs[s][n];
            }
            yv += ut * Dv;
            float z = g_uz[(size_t)tok * (2 * DI) + DI + d];
            g_y[(size_t)tok * DI + d] = yv * (z / (1.f + __expf(-z)));
        }
    }
}

// ---------------- x += LayerNorm(g_t) ----------------
__global__ void addln_k(const float* __restrict__ g, const float* __restrict__ bb) {
    int tok = blockIdx.x;
    const float* t = g_t + (size_t)tok * DM;
    float* x = g_x + (size_t)tok * DM;
    int tid = threadIdx.x;
    float v[4]; float s = 0.f;
#pragma unroll
    for (int i = 0; i < 4; i++) { v[i] = t[tid + i * 256]; s += v[i]; }
    __shared__ float sm[256];
    sm[tid] = s; __syncthreads();
    for (int st = 128; st > 0; st >>= 1) { if (tid < st) sm[tid] += sm[tid + st]; __syncthreads(); }
    float mean = sm[0] / DM;
    __syncthreads();
    float q = 0.f;
#pragma unroll
    for (int i = 0; i < 4; i++) { float dd = v[i] - mean; q += dd * dd; }
    sm[tid] = q; __syncthreads();
    for (int st = 128; st > 0; st >>= 1) { if (tid < st) sm[tid] += sm[tid + st]; __syncthreads(); }
    float rstd = rsqrtf(sm[0] / DM + 1e-5f);
#pragma unroll
    for (int i = 0; i < 4; i++) {
        int d = tid + i * 256;
        x[d] += (v[i] - mean) * rstd * g[d] + bb[d];
    }
}

// ---------------- MoE gate: top-1 routing ----------------
__global__ void gate_k(const float* __restrict__ gw, const float* __restrict__ gb) {
    int tok = blockIdx.x;
    const float* x = g_x + (size_t)tok * DM;
    int tid = threadIdx.x;
    float p[NEXP];
#pragma unroll
    for (int e = 0; e < NEXP; e++) p[e] = 0.f;
    for (int d = tid; d < DM; d += 256) {
        float xv = x[d];
#pragma unroll
        for (int e = 0; e < NEXP; e++) p[e] += xv * gw[e * DM + d];
    }
    __shared__ float sm[NEXP][256];
#pragma unroll
    for (int e = 0; e < NEXP; e++) sm[e][tid] = p[e];
    __syncthreads();
    for (int st = 128; st > 0; st >>= 1) {
        if (tid < st)
#pragma unroll
            for (int e = 0; e < NEXP; e++) sm[e][tid] += sm[e][tid + st];
        __syncthreads();
    }
    if (tid == 0) {
        float m = -1e30f; int bi = 0;
        float lg[NEXP];
#pragma unroll
        for (int e = 0; e < NEXP; e++) {
            lg[e] = sm[e][0] + gb[e];
            if (lg[e] > m) { m = lg[e]; bi = e; }
        }
        float ssum = 0.f;
#pragma unroll
        for (int e = 0; e < NEXP; e++) ssum += __expf(lg[e] - m);
        g_eidx[tok] = bi;
        g_ew[tok] = 1.f / ssum;        // softmax max prob
        atomicAdd(&g_cnt[bi], 1);
    }
}

__global__ void route_reset_k() { if (threadIdx.x < NEXP) { g_cnt[threadIdx.x] = 0; g_fill[threadIdx.x] = 0; } }
__global__ void route_offsets_k() {
    if (threadIdx.x == 0) { int o = 0; for (int e = 0; e < NEXP; e++) { g_off[e] = o; o += g_cnt[e]; } }
}
__global__ void route_scatter_k() {
    int tok = blockIdx.x * 256 + threadIdx.x;
    if (tok < NTOK) {
        int e = g_eidx[tok];
        int p = g_off[e] + atomicAdd(&g_fill[e], 1);
        g_perm[p] = tok;
    }
}

// ---------------- pooling + head ----------------
__global__ void cntb_reset_k() { if (threadIdx.x < BATCH) g_cntb[threadIdx.x] = 0; }

__global__ void rowmask_k() {
    int tok = blockIdx.x;
    int tid = threadIdx.x;
    float s = 0.f;
#pragma unroll
    for (int i = 0; i < 4; i++) s += g_x[(size_t)tok * DM + tid + i * 256];
    __shared__ float sm[256];
    sm[tid] = s; __syncthreads();
    for (int st = 128; st > 0; st >>= 1) { if (tid < st) sm[tid] += sm[tid + st]; __syncthreads(); }
    if (tid == 0) {
        float m = (sm[0] != 0.f) ? 1.f : 0.f;
        g_mask[tok] = m;
        if (m != 0.f) atomicAdd(&g_cntb[tok / LSEQ], 1);
    }
}

__global__ void pool_k() {
    int b = blockIdx.x;
    int d = blockIdx.y * 256 + threadIdx.x;
    float acc = 0.f;
    for (int l = 0; l < LSEQ; l++)
        acc += g_x[(size_t)(b * LSEQ + l) * DM + d] * g_mask[b * LSEQ + l];
    g_pooled[b * DM + d] = acc / fmaxf((float)g_cntb[b], 1.f);
}

__global__ void head_k(const float* __restrict__ w1, const float* __restrict__ b1,
                       const float* __restrict__ w2, const float* __restrict__ b2,
                       float* __restrict__ out) {
    int b = blockIdx.x;
    int j = threadIdx.x;   // 128
    const float* p = g_pooled + b * DM;
    float acc = b1[j];
    for (int k = 0; k < DM; k++) acc += p[k] * w1[j * DM + k];
    __shared__ float h[128];
    h[j] = fmaxf(acc, 0.f);
    __syncthreads();
    if (j < 2) {
        float o = b2[j];
        for (int k = 0; k < 128; k++) o += h[k] * w2[j * 128 + k];
        out[b * 2 + j] = o;
    }
}

// ---------------- launch ----------------
extern "C" void kernel_launch(void* const* d_in, const int* in_sizes, int n_in,
                              void* d_out, int out_size) {
    const int*   tok    = (const int*)  d_in[0];
    const float* emb    = (const float*)d_in[1];
    const float* pos    = (const float*)d_in[2];
    const float* in_w   = (const float*)d_in[3];
    const float* conv_w = (const float*)d_in[4];
    const float* conv_b = (const float*)d_in[5];
    const float* xp_w   = (const float*)d_in[6];
    const float* dt_w   = (const float*)d_in[7];
    const float* dt_b   = (const float*)d_in[8];
    const float* A_log  = (const float*)d_in[9];
    const float* D_ssm  = (const float*)d_in[10];
    const float* out_w  = (const float*)d_in[11];
    const float* ln1_g  = (const float*)d_in[12];
    const float* ln1_b  = (const float*)d_in[13];
    const float* ln2_g  = (const float*)d_in[14];
    const float* ln2_b  = (const float*)d_in[15];
    const float* gate_w = (const float*)d_in[16];
    const float* gate_b = (const float*)d_in[17];
    const float* e_w1   = (const float*)d_in[18];
    const float* e_b1   = (const float*)d_in[19];
    const float* e_w2   = (const float*)d_in[20];
    const float* e_b2   = (const float*)d_in[21];
    const float* fc1_w  = (const float*)d_in[22];
    const float* fc1_b  = (const float*)d_in[23];
    const float* fc2_w  = (const float*)d_in[24];
    const float* fc2_b  = (const float*)d_in[25];
    float* out = (float*)d_out;

    float *px, *puz, *pu, *pxp, *pdt, *py, *pt, *ph, *pew;
    int *pcnt, *poff, *pperm;
    cudaGetSymbolAddress((void**)&px,   g_x);
    cudaGetSymbolAddress((void**)&puz,  g_uz);
    cudaGetSymbolAddress((void**)&pu,   g_u);
    cudaGetSymbolAddress((void**)&pxp,  g_xp);
    cudaGetSymbolAddress((void**)&pdt,  g_dt);
    cudaGetSymbolAddress((void**)&py,   g_y);
    cudaGetSymbolAddress((void**)&pt,   g_t);
    cudaGetSymbolAddress((void**)&ph,   g_h);
    cudaGetSymbolAddress((void**)&pew,  g_ew);
    cudaGetSymbolAddress((void**)&pcnt, g_cnt);
    cudaGetSymbolAddress((void**)&poff, g_off);
    cudaGetSymbolAddress((void**)&pperm,g_perm);

    embed_k<<<(NTOK * DM) / 256, 256>>>(tok, emb, pos);

    for (int l = 0; l < 2; l++) {
        const float* in_w_l   = in_w   + (size_t)l * (2 * DI) * DM;
        const float* conv_w_l = conv_w + (size_t)l * DI * 4;
        const float* conv_b_l = conv_b + (size_t)l * DI;
        const float* xp_w_l   = xp_w   + (size_t)l * XPD * DI;
        const float* dt_w_l   = dt_w   + (size_t)l * DI * DTR;
        const float* dt_b_l   = dt_b   + (size_t)l * DI;
        const float* A_log_l  = A_log  + (size_t)l * DI * DS;
        const float* D_l      = D_ssm  + (size_t)l * DI;
        const float* out_w_l  = out_w  + (size_t)l * DM * DI;
        const float* ln1_g_l  = ln1_g  + (size_t)l * DM;
        const float* ln1_b_l  = ln1_b  + (size_t)l * DM;
        const float* ln2_g_l  = ln2_g  + (size_t)l * DM;
        const float* ln2_b_l  = ln2_b  + (size_t)l * DM;
        const float* gate_w_l = gate_w + (size_t)l * NEXP * DM;
        const float* gate_b_l = gate_b + (size_t)l * NEXP;
        const float* e_w1_l   = e_w1   + (size_t)l * NEXP * HEXP * DM;
        const float* e_b1_l   = e_b1   + (size_t)l * NEXP * HEXP;
        const float* e_w2_l   = e_w2   + (size_t)l * NEXP * DM * HEXP;
        const float* e_b2_l   = e_b2   + (size_t)l * NEXP * DM;

        // 1) uz = x @ in_w^T                        [4096,4096]
        gemm_tn<<<dim3(32, 32, 1), 256>>>(px, DM, in_w_l, DM, 0, puz, 2 * DI,
                                          nullptr, 0, NTOK, nullptr, nullptr, nullptr, nullptr,
                                          0, 2 * DI, DM, 0);
        // 2) u = silu(causal_conv(u))
        conv_silu_k<<<(NTOK * DI) / 256, 256>>>(conv_w_l, conv_b_l);
        // 3) xp = u @ xp_w^T                        [4096,96]
        gemm_tn<<<dim3(32, 1, 1), 256>>>(pu, DI, xp_w_l, DI, 0, pxp, XPD,
                                         nullptr, 0, NTOK, nullptr, nullptr, nullptr, nullptr,
                                         0, XPD, DI, 0);
        // 4) dt = softplus(xp[:, :64] @ dt_w^T + dt_b)   [4096,2048]
        gemm_tn<<<dim3(32, 16, 1), 256>>>(pxp, XPD, dt_w_l, DTR, 0, pdt, DI,
                                          dt_b_l, 0, NTOK, nullptr, nullptr, nullptr, nullptr,
                                          0, DI, DTR, 2);
        // 5) selective scan -> g_y = ssm(...) * silu(z)
        ssm_scan_k<<<dim3(BATCH, DI / 256), 256>>>(A_log_l, D_l);
        // 6) mamba out = y @ out_w^T                [4096,1024]
        gemm_tn<<<dim3(32, 8, 1), 256>>>(py, DI, out_w_l, DI, 0, pt, DM,
                                         nullptr, 0, NTOK, nullptr, nullptr, nullptr, nullptr,
                                         0, DM, DI, 0);
        // 7) x += LN(mamba_out)
        addln_k<<<NTOK, 256>>>(ln1_g_l, ln1_b_l);

        // 8) MoE routing
        route_reset_k<<<1, 32>>>();
        gate_k<<<NTOK, 256>>>(gate_w_l, gate_b_l);
        route_offsets_k<<<1, 1>>>();
        route_scatter_k<<<NTOK / 256, 256>>>();
        // 9) h = relu(gather(x) @ w1[e]^T + b1[e])
        gemm_tn<<<dim3(32, 8, NEXP), 256>>>(px, DM, e_w1_l, DM, (size_t)HEXP * DM, ph, HEXP,
                                            e_b1_l, HEXP, 0, pcnt, poff, pperm, nullptr,
                                            1, HEXP, DM, 1);
        // 10) moe_out = scatter(topw * (h @ w2[e]^T + b2[e]))
        gemm_tn<<<dim3(32, 8, NEXP), 256>>>(ph, HEXP, e_w2_l, HEXP, (size_t)DM * HEXP, pt, DM,
                                            e_b2_l, DM, 0, pcnt, poff, pperm, pew,
                                            2, DM, HEXP, 0);
        // 11) x += LN(moe_out)
        addln_k<<<NTOK, 256>>>(ln2_g_l, ln2_b_l);
    }

    // pooling + head
    cntb_reset_k<<<1, 32>>>();
    rowmask_k<<<NTOK, 256>>>();
    pool_k<<<dim3(BATCH, DM / 256), 256>>>();
    head_k<<<BATCH, 128>>>(fc1_w, fc1_b, fc2_w, fc2_b, out);
}

// round 3
// speedup vs baseline: 1.5800x; 1.5800x over previous
#include <cuda_runtime.h>
#include <cuda_bf16.h>
#include <math.h>
#include <stdint.h>

// ---------------- problem constants ----------------
#define NTOK  4096            // B*L
#define LSEQ  1024
#define BATCH 4
#define DM    1024
#define DI    2048
#define DS    16
#define DTR   64
#define XPD   96              // DTR + 2*DS
#define NEXP  8
#define HEXP  1024

// ---------------- device scratch ----------------
__device__ float g_x [NTOK*DM];
__device__ float g_uz[NTOK*2*DI];
__device__ float g_u [NTOK*DI];
__device__ float g_xp[NTOK*XPD];
__device__ float g_dt[NTOK*DI];
__device__ float g_t [NTOK*DM];
__device__ float g_mask[NTOK];
__device__ float g_pooled[BATCH*DM];
__device__ int   g_eidx[NTOK];
__device__ float g_ew  [NTOK];
__device__ int   g_perm[NTOK];
__device__ int   g_cnt[NEXP], g_off[NEXP], g_fill[NEXP], g_cntb[BATCH];

// bf16 hi/lo split buffers
__device__ __nv_bfloat16 g_xh[NTOK*DM],  g_xl[NTOK*DM];
__device__ __nv_bfloat16 g_uh[NTOK*DI],  g_ul[NTOK*DI];
__device__ __nv_bfloat16 g_yh[NTOK*DI],  g_yl[NTOK*DI];
__device__ __nv_bfloat16 g_hh[NTOK*HEXP],g_hl[NTOK*HEXP];
__device__ __nv_bfloat16 g_dah[NTOK*DTR],g_dal[NTOK*DTR];
__device__ __nv_bfloat16 g_wh[NEXP*HEXP*DM], g_wl[NEXP*HEXP*DM];

// ---------------- PTX helpers (base ISA only: sm_80-compatible) ----------------
__device__ __forceinline__ uint32_t smem_u32(const void* p) {
    uint32_t a;
    asm("{ .reg .u64 t; cvta.to.shared.u64 t, %1; cvt.u32.u64 %0, t; }" : "=r"(a) : "l"(p));
    return a;
}
__device__ __forceinline__ void ldsm4(uint32_t* r, uint32_t addr) {
    asm volatile("ldmatrix.sync.aligned.m8n8.x4.shared.b16 {%0,%1,%2,%3}, [%4];"
        : "=r"(r[0]), "=r"(r[1]), "=r"(r[2]), "=r"(r[3]) : "r"(addr));
}
__device__ __forceinline__ void mma_bf16(float* c, const uint32_t* a, uint32_t b0, uint32_t b1) {
    asm volatile("mma.sync.aligned.m16n8k16.row.col.f32.bf16.bf16.f32 "
        "{%0,%1,%2,%3}, {%4,%5,%6,%7}, {%8,%9}, {%0,%1,%2,%3};"
        : "+f"(c[0]), "+f"(c[1]), "+f"(c[2]), "+f"(c[3])
        : "r"(a[0]), "r"(a[1]), "r"(a[2]), "r"(a[3]), "r"(b0), "r"(b1));
}
__device__ __forceinline__ void cpa16(uint32_t saddr, const void* g, bool v) {
    int sz = v ? 16 : 0;
    asm volatile("cp.async.cg.shared.global [%0], [%1], 16, %2;"
        :: "r"(saddr), "l"(g), "r"(sz));
}
#define CP_COMMIT() asm volatile("cp.async.commit_group;" ::: "memory")
#define CP_WAIT1()  asm volatile("cp.async.wait_group 1;" ::: "memory")

// smem geometry: row = 32 bf16 padded to 40 (80B) for conflict-free ldmatrix
#define ROWB   80
#define ATILE  10240              // 128 * 80
#define STAGEB 20480              // A + B tile
#define SM_TOT 61440              // 3 stages

// ============ bf16 mma.sync GEMM: C[M,N] = act(A @ W^T + bias) ============
// hi/lo split: 3 K-segments (Ah,Wh), (Ah,Wl), (Al,Wh) accumulated in fp32.
// mode 0: dense. mode 1: gather A rows via perm (C compact). mode 2: A compact, scatter C via perm w/ rowscale.
__global__ void __launch_bounds__(256, 2)
mma_gemm(const __nv_bfloat16* __restrict__ Ah, const __nv_bfloat16* __restrict__ Al, int lda,
         const __nv_bfloat16* __restrict__ Wh, const __nv_bfloat16* __restrict__ Wl, int ldw, size_t wz,
         float* __restrict__ C, int ldc,
         __nv_bfloat16* __restrict__ Ch, __nv_bfloat16* __restrict__ Cl,
         const float* __restrict__ bias, int bias_z,
         int M_fixed, const int* __restrict__ cntp, const int* __restrict__ offp,
         const int* __restrict__ perm, const float* __restrict__ rowscale,
         int mode, int N, int K, int act)
{
    int e = blockIdx.z;
    int M = cntp ? cntp[e] : M_fixed;
    int base = offp ? offp[e] : 0;
    int m0 = blockIdx.x * 128;
    if (m0 >= M) return;
    int n0 = blockIdx.y * 128;

    extern __shared__ char smem[];
    uint32_t sb = smem_u32(smem);
    int tid = threadIdx.x;

    // ---- copy mapping: 1024 x 16B chunks/stage; thread -> 2 A rows + 2 B rows ----
    int sub = tid & 3;            // which 16B of the 64B row
    int r0 = tid >> 2;            // 0..63
    int r1 = r0 + 64;

    long ar0, ar1; bool av0, av1;
    {
        int mm0 = m0 + r0, mm1 = m0 + r1;
        av0 = mm0 < M; av1 = mm1 < M;
        if (mode == 1) { ar0 = av0 ? (long)perm[base + mm0] : 0; ar1 = av1 ? (long)perm[base + mm1] : 0; }
        else if (mode == 2) { ar0 = base + (av0 ? mm0 : 0); ar1 = base + (av1 ? mm1 : 0); }
        else { ar0 = av0 ? mm0 : 0; ar1 = av1 ? mm1 : 0; }
    }
    int nr0 = n0 + r0, nr1 = n0 + r1;
    bool wv0 = nr0 < N, wv1 = nr1 < N;
    if (!wv0) nr0 = 0;
    if (!wv1) nr1 = 0;

    const __nv_bfloat16* WhE = Wh + (size_t)e * wz;
    const __nv_bfloat16* WlE = Wl + (size_t)e * wz;

    size_t aoff0 = (size_t)ar0 * lda + sub * 8;
    size_t aoff1 = (size_t)ar1 * lda + sub * 8;
    size_t woff0 = (size_t)nr0 * ldw + sub * 8;
    size_t woff1 = (size_t)nr1 * ldw + sub * 8;

    uint32_t smA0 = sb + r0 * ROWB + sub * 16;
    uint32_t smA1 = sb + r1 * ROWB + sub * 16;

    const int NKC = K / 32;
    const int NC = 3 * NKC;

#define COPY_STAGE(c, s) do { \
        int _seg = (c) / NKC; int _k0 = ((c) - _seg * NKC) * 32; \
        const __nv_bfloat16* _Ap = (_seg == 2) ? Al : Ah; \
        const __nv_bfloat16* _Wp = (_seg == 1) ? WlE : WhE; \
        uint32_t _sb = (uint32_t)(s) * STAGEB; \
        cpa16(smA0 + _sb,          _Ap + aoff0 + _k0, av0); \
        cpa16(smA1 + _sb,          _Ap + aoff1 + _k0, av1); \
        cpa16(smA0 + _sb + ATILE,  _Wp + woff0 + _k0, wv0); \
        cpa16(smA1 + _sb + ATILE,  _Wp + woff1 + _k0, wv1); \
    } while (0)

    // ---- mma mapping ----
    int lane = tid & 31;
    int wid = tid >> 5;
    int wm = (wid & 3) * 32;
    int wn = (wid >> 2) * 64;

    int aRow = wm + (lane & 7) + ((lane >> 3) & 1) * 8;
    uint32_t aColB = ((lane >> 4) & 1) * 16;
    int bRow = wn + (lane & 7) + ((lane >> 4) & 1) * 8;
    uint32_t bColB = ((lane >> 3) & 1) * 16;

    float acc[2][8][4] = {};

    // prologue: 2 stages in flight
    COPY_STAGE(0, 0); CP_COMMIT();
    COPY_STAGE(1, 1); CP_COMMIT();

    for (int c = 0; c < NC; c++) {
        CP_WAIT1();
        __syncthreads();
        if (c + 2 < NC) COPY_STAGE(c + 2, (c + 2) % 3);
        CP_COMMIT();

        uint32_t Ab = sb + (uint32_t)(c % 3) * STAGEB;
        uint32_t Bb = Ab + ATILE;
#pragma unroll
        for (int st = 0; st < 2; st++) {
            uint32_t kB = st * 32;
            uint32_t a[2][4], b[4][4];
#pragma unroll
            for (int im = 0; im < 2; im++)
                ldsm4(a[im], Ab + (uint32_t)(aRow + im * 16) * ROWB + kB + aColB);
#pragma unroll
            for (int g = 0; g < 4; g++)
                ldsm4(b[g], Bb + (uint32_t)(bRow + g * 16) * ROWB + kB + bColB);
#pragma unroll
            for (int im = 0; im < 2; im++)
#pragma unroll
                for (int in = 0; in < 8; in++)
                    mma_bf16(acc[im][in], a[im], b[in >> 1][(in & 1) * 2], b[in >> 1][(in & 1) * 2 + 1]);
        }
    }

    // ---- epilogue ----
    int lq = lane >> 2;          // row within 8
    int lr = lane & 3;           // col pair
    const float* bp = bias ? (bias + (size_t)e * bias_z) : nullptr;
#pragma unroll
    for (int im = 0; im < 2; im++) {
#pragma unroll
        for (int r2 = 0; r2 < 2; r2++) {
            int m = m0 + wm + im * 16 + lq + r2 * 8;
            if (m >= M) continue;
            long crow; float scale = 1.f;
            if (mode == 2)      { crow = perm[base + m]; scale = rowscale[crow]; }
            else if (mode == 1) { crow = base + m; }
            else                { crow = m; }
#pragma unroll
            for (int in = 0; in < 8; in++) {
                int n = n0 + wn + in * 8 + lr * 2;
                if (n >= N) continue;
                float v0 = acc[im][in][r2 * 2 + 0];
                float v1 = acc[im][in][r2 * 2 + 1];
                if (bp) { v0 += bp[n]; v1 += bp[n + 1]; }
                if (act == 1) { v0 = fmaxf(v0, 0.f); v1 = fmaxf(v1, 0.f); }
                else if (act == 2) {
                    v0 = (v0 > 20.f) ? v0 : log1pf(__expf(v0));
                    v1 = (v1 > 20.f) ? v1 : log1pf(__expf(v1));
                }
                if (Ch) {
                    __nv_bfloat16 h0 = __float2bfloat16(v0);
                    __nv_bfloat16 h1 = __float2bfloat16(v1);
                    size_t o = (size_t)crow * ldc + n;
                    Ch[o] = h0;     Cl[o]     = __float2bfloat16(v0 - __bfloat162float(h0));
                    Ch[o + 1] = h1; Cl[o + 1] = __float2bfloat16(v1 - __bfloat162float(h1));
                } else {
                    size_t o = (size_t)crow * ldc + n;
                    C[o] = v0 * scale;
                    C[o + 1] = v1 * scale;
                }
            }
        }
    }
#undef COPY_STAGE
}

// ---------------- hi/lo split helpers ----------------
__device__ __forceinline__ void split2(float v, __nv_bfloat16& h, __nv_bfloat16& l) {
    h = __float2bfloat16(v);
    l = __float2bfloat16(v - __bfloat162float(h));
}

__global__ void wconv_k(const float* __restrict__ w, __nv_bfloat16* __restrict__ h,
                        __nv_bfloat16* __restrict__ l, int n) {
    int i = blockIdx.x * 256 + threadIdx.x;
    if (i >= n) return;
    split2(w[i], h[i], l[i]);
}

__global__ void dtconv_k() {  // xp[:, :DTR] -> g_dah/g_dal (compact)
    int i = blockIdx.x * 256 + threadIdx.x;   // NTOK*DTR
    int t = i >> 6, c = i & 63;
    split2(g_xp[t * XPD + c], g_dah[i], g_dal[i]);
}

// ---------------- embed ----------------
__global__ void embed_k(const int* __restrict__ tok, const float* __restrict__ emb,
                        const float* __restrict__ pos) {
    int i = blockIdx.x * blockDim.x + threadIdx.x;
    int t = i / DM, d = i % DM;
    int l = t % LSEQ;
    float v = emb[(size_t)tok[t] * DM + d] + pos[l * DM + d];
    g_x[i] = v;
    split2(v, g_xh[i], g_xl[i]);
}

// ---------------- conv + silu ----------------
__global__ void conv_silu_k(const float* __restrict__ cw, const float* __restrict__ cb) {
    int i = blockIdx.x * 256 + threadIdx.x;
    if (i >= NTOK * DI) return;
    int t = i / DI, d = i % DI;
    int b = t / LSEQ, l = t % LSEQ;
    float acc = cb[d];
#pragma unroll
    for (int k = 0; k < 4; k++) {
        int ll = l - 3 + k;
        if (ll >= 0) acc += g_uz[(size_t)(b * LSEQ + ll) * (2 * DI) + d] * cw[d * 4 + k];
    }
    float v = acc / (1.f + __expf(-acc));
    g_u[i] = v;
    split2(v, g_uh[i], g_ul[i]);
}

// ---------------- selective scan ----------------
__global__ void __launch_bounds__(128) ssm_scan_k(const float* __restrict__ A_log,
                                                  const float* __restrict__ Dp) {
    int b = blockIdx.x;
    int d = blockIdx.y * 128 + threadIdx.x;
    float A[DS];
#pragma unroll
    for (int n = 0; n < DS; n++) A[n] = -expf(A_log[d * DS + n]);
    float Dv = Dp[d];
    float h[DS];
#pragma unroll
    for (int n = 0; n < DS; n++) h[n] = 0.f;

    __shared__ float Bs[64][DS], Cs[64][DS];

    for (int c = 0; c < LSEQ / 64; c++) {
        __syncthreads();
        for (int i = threadIdx.x; i < 64 * DS; i += 128) {
            int s = i / DS, n = i % DS;
            int tok = b * LSEQ + c * 64 + s;
            Bs[s][n] = g_xp[tok * XPD + DTR + n];
            Cs[s][n] = g_xp[tok * XPD + DTR + DS + n];
        }
        __syncthreads();
        for (int s = 0; s < 64; s++) {
            int tok = b * LSEQ + c * 64 + s;
            float ut  = g_u [(size_t)tok * DI + d];
            float dtt = g_dt[(size_t)tok * DI + d];
            float du = dtt * ut;
            float yv = 0.f;
#pragma unroll
            for (int n = 0; n < DS; n++) {
                h[n] = __expf(dtt * A[n]) * h[n] + du * Bs[s][n];
                yv += h[n] * Cs[s][n];
            }
            yv += ut * Dv;
            float z = g_uz[(size_t)tok * (2 * DI) + DI + d];
            float y = yv * (z / (1.f + __expf(-z)));
            size_t o = (size_t)tok * DI + d;
            split2(y, g_yh[o], g_yl[o]);
        }
    }
}

// ---------------- x += LayerNorm(g_t), refresh hi/lo ----------------
__global__ void addln_k(const float* __restrict__ g, const float* __restrict__ bb) {
    int tok = blockIdx.x;
    const float* t = g_t + (size_t)tok * DM;
    float* x = g_x + (size_t)tok * DM;
    int tid = threadIdx.x;
    float v[4]; float s = 0.f;
#pragma unroll
    for (int i = 0; i < 4; i++) { v[i] = t[tid + i * 256]; s += v[i]; }
    __shared__ float sm[256];
    sm[tid] = s; __syncthreads();
    for (int st = 128; st > 0; st >>= 1) { if (tid < st) sm[tid] += sm[tid + st]; __syncthreads(); }
    float mean = sm[0] / DM;
    __syncthreads();
    float q = 0.f;
#pragma unroll
    for (int i = 0; i < 4; i++) { float dd = v[i] - mean; q += dd * dd; }
    sm[tid] = q; __syncthreads();
    for (int st = 128; st > 0; st >>= 1) { if (tid < st) sm[tid] += sm[tid + st]; __syncthreads(); }
    float rstd = rsqrtf(sm[0] / DM + 1e-5f);
#pragma unroll
    for (int i = 0; i < 4; i++) {
        int d = tid + i * 256;
        float nx = x[d] + (v[i] - mean) * rstd * g[d] + bb[d];
        x[d] = nx;
        split2(nx, g_xh[(size_t)tok * DM + d], g_xl[(size_t)tok * DM + d]);
    }
}

// ---------------- MoE gate ----------------
__global__ void gate_k(const float* __restrict__ gw, const float* __restrict__ gb) {
    int tok = blockIdx.x;
    const float* x = g_x + (size_t)tok * DM;
    int tid = threadIdx.x;
    float p[NEXP];
#pragma unroll
    for (int e = 0; e < NEXP; e++) p[e] = 0.f;
    for (int d = tid; d < DM; d += 256) {
        float xv = x[d];
#pragma unroll
        for (int e = 0; e < NEXP; e++) p[e] += xv * gw[e * DM + d];
    }
    __shared__ float sm[NEXP][256];
#pragma unroll
    for (int e = 0; e < NEXP; e++) sm[e][tid] = p[e];
    __syncthreads();
    for (int st = 128; st > 0; st >>= 1) {
        if (tid < st)
#pragma unroll
            for (int e = 0; e < NEXP; e++) sm[e][tid] += sm[e][tid + st];
        __syncthreads();
    }
    if (tid == 0) {
        float m = -1e30f; int bi = 0;
        float lg[NEXP];
#pragma unroll
        for (int e = 0; e < NEXP; e++) {
            lg[e] = sm[e][0] + gb[e];
            if (lg[e] > m) { m = lg[e]; bi = e; }
        }
        float ssum = 0.f;
#pragma unroll
        for (int e = 0; e < NEXP; e++) ssum += __expf(lg[e] - m);
        g_eidx[tok] = bi;
        g_ew[tok] = 1.f / ssum;
        atomicAdd(&g_cnt[bi], 1);
    }
}

__global__ void route_reset_k() { if (threadIdx.x < NEXP) { g_cnt[threadIdx.x] = 0; g_fill[threadIdx.x] = 0; } }
__global__ void route_offsets_k() {
    if (threadIdx.x == 0) { int o = 0; for (int e = 0; e < NEXP; e++) { g_off[e] = o; o += g_cnt[e]; } }
}
__global__ void route_scatter_k() {
    int tok = blockIdx.x * 256 + threadIdx.x;
    if (tok < NTOK) {
        int e = g_eidx[tok];
        int p = g_off[e] + atomicAdd(&g_fill[e], 1);
        g_perm[p] = tok;
    }
}

// ---------------- pooling + head ----------------
__global__ void cntb_reset_k() { if (threadIdx.x < BATCH) g_cntb[threadIdx.x] = 0; }

__global__ void rowmask_k() {
    int tok = blockIdx.x;
    int tid = threadIdx.x;
    float s = 0.f;
#pragma unroll
    for (int i = 0; i < 4; i++) s += g_x[(size_t)tok * DM + tid + i * 256];
    __shared__ float sm[256];
    sm[tid] = s; __syncthreads();
    for (int st = 128; st > 0; st >>= 1) { if (tid < st) sm[tid] += sm[tid + st]; __syncthreads(); }
    if (tid == 0) {
        float m = (sm[0] != 0.f) ? 1.f : 0.f;
        g_mask[tok] = m;
        if (m != 0.f) atomicAdd(&g_cntb[tok / LSEQ], 1);
    }
}

__global__ void pool_k() {
    int b = blockIdx.x;
    int d = blockIdx.y * 256 + threadIdx.x;
    float acc = 0.f;
    for (int l = 0; l < LSEQ; l++)
        acc += g_x[(size_t)(b * LSEQ + l) * DM + d] * g_mask[b * LSEQ + l];
    g_pooled[b * DM + d] = acc / fmaxf((float)g_cntb[b], 1.f);
}

__global__ void head_k(const float* __restrict__ w1, const float* __restrict__ b1,
                       const float* __restrict__ w2, const float* __restrict__ b2,
                       float* __restrict__ out) {
    int b = blockIdx.x;
    int j = threadIdx.x;
    const float* p = g_pooled + b * DM;
    float acc = b1[j];
    for (int k = 0; k < DM; k++) acc += p[k] * w1[j * DM + k];
    __shared__ float h[128];
    h[j] = fmaxf(acc, 0.f);
    __syncthreads();
    if (j < 2) {
        float o = b2[j];
        for (int k = 0; k < 128; k++) o += h[k] * w2[j * 128 + k];
        out[b * 2 + j] = o;
    }
}

// ---------------- launch ----------------
extern "C" void kernel_launch(void* const* d_in, const int* in_sizes, int n_in,
                              void* d_out, int out_size) {
    const int*   tok    = (const int*)  d_in[0];
    const float* emb    = (const float*)d_in[1];
    const float* pos    = (const float*)d_in[2];
    const float* in_w   = (const float*)d_in[3];
    const float* conv_w = (const float*)d_in[4];
    const float* conv_b = (const float*)d_in[5];
    const float* xp_w   = (const float*)d_in[6];
    const float* dt_w   = (const float*)d_in[7];
    const float* dt_b   = (const float*)d_in[8];
    const float* A_log  = (const float*)d_in[9];
    const float* D_ssm  = (const float*)d_in[10];
    const float* out_w  = (const float*)d_in[11];
    const float* ln1_g  = (const float*)d_in[12];
    const float* ln1_b  = (const float*)d_in[13];
    const float* ln2_g  = (const float*)d_in[14];
    const float* ln2_b  = (const float*)d_in[15];
    const float* gate_w = (const float*)d_in[16];
    const float* gate_b = (const float*)d_in[17];
    const float* e_w1   = (const float*)d_in[18];
    const float* e_b1   = (const float*)d_in[19];
    const float* e_w2   = (const float*)d_in[20];
    const float* e_b2   = (const float*)d_in[21];
    const float* fc1_w  = (const float*)d_in[22];
    const float* fc1_b  = (const float*)d_in[23];
    const float* fc2_w  = (const float*)d_in[24];
    const float* fc2_b  = (const float*)d_in[25];
    float* out = (float*)d_out;

    cudaFuncSetAttribute(mma_gemm, cudaFuncAttributeMaxDynamicSharedMemorySize, SM_TOT);

    float *puz, *pxp, *pdt, *pt, *pew;
    __nv_bfloat16 *pxh, *pxl, *puh, *pul, *pyh, *pyl, *phh, *phl, *pdah, *pdal, *pwh, *pwl;
    int *pcnt, *poff, *pperm;
    cudaGetSymbolAddress((void**)&puz,  g_uz);
    cudaGetSymbolAddress((void**)&pxp,  g_xp);
    cudaGetSymbolAddress((void**)&pdt,  g_dt);
    cudaGetSymbolAddress((void**)&pt,   g_t);
    cudaGetSymbolAddress((void**)&pew,  g_ew);
    cudaGetSymbolAddress((void**)&pxh,  g_xh);
    cudaGetSymbolAddress((void**)&pxl,  g_xl);
    cudaGetSymbolAddress((void**)&puh,  g_uh);
    cudaGetSymbolAddress((void**)&pul,  g_ul);
    cudaGetSymbolAddress((void**)&pyh,  g_yh);
    cudaGetSymbolAddress((void**)&pyl,  g_yl);
    cudaGetSymbolAddress((void**)&phh,  g_hh);
    cudaGetSymbolAddress((void**)&phl,  g_hl);
    cudaGetSymbolAddress((void**)&pdah, g_dah);
    cudaGetSymbolAddress((void**)&pdal, g_dal);
    cudaGetSymbolAddress((void**)&pwh,  g_wh);
    cudaGetSymbolAddress((void**)&pwl,  g_wl);
    cudaGetSymbolAddress((void**)&pcnt, g_cnt);
    cudaGetSymbolAddress((void**)&poff, g_off);
    cudaGetSymbolAddress((void**)&pperm,g_perm);

    embed_k<<<(NTOK * DM) / 256, 256>>>(tok, emb, pos);

    for (int l = 0; l < 2; l++) {
        const float* in_w_l   = in_w   + (size_t)l * (2 * DI) * DM;
        const float* conv_w_l = conv_w + (size_t)l * DI * 4;
        const float* conv_b_l = conv_b + (size_t)l * DI;
        const float* xp_w_l   = xp_w   + (size_t)l * XPD * DI;
        const float* dt_w_l   = dt_w   + (size_t)l * DI * DTR;
        const float* dt_b_l   = dt_b   + (size_t)l * DI;
        const float* A_log_l  = A_log  + (size_t)l * DI * DS;
        const float* D_l      = D_ssm  + (size_t)l * DI;
        const float* out_w_l  = out_w  + (size_t)l * DM * DI;
        const float* e_w1_l   = e_w1   + (size_t)l * NEXP * HEXP * DM;
        const float* e_b1_l   = e_b1   + (size_t)l * NEXP * HEXP;
        const float* e_w2_l   = e_w2   + (size_t)l * NEXP * DM * HEXP;
        const float* e_b2_l   = e_b2   + (size_t)l * NEXP * DM;

        // in_proj: uz = x @ in_w^T     [4096 x 4096], K=1024
        wconv_k<<<(2 * DI * DM + 255) / 256, 256>>>(in_w_l, pwh, pwl, 2 * DI * DM);
        mma_gemm<<<dim3(32, 32, 1), 256, SM_TOT>>>(
            pxh, pxl, DM, pwh, pwl, DM, 0, puz, 2 * DI, nullptr, nullptr,
            nullptr, 0, NTOK, nullptr, nullptr, nullptr, nullptr, 0, 2 * DI, DM, 0);

        conv_silu_k<<<(NTOK * DI) / 256, 256>>>(conv_w_l, conv_b_l);

        // xp = u @ xp_w^T              [4096 x 96], K=2048
        wconv_k<<<(XPD * DI + 255) / 256, 256>>>(xp_w_l, pwh, pwl, XPD * DI);
        mma_gemm<<<dim3(32, 1, 1), 256, SM_TOT>>>(
            puh, pul, DI, pwh, pwl, DI, 0, pxp, XPD, nullptr, nullptr,
            nullptr, 0, NTOK, nullptr, nullptr, nullptr, nullptr, 0, XPD, DI, 0);

        // dt = softplus(xp[:,:64] @ dt_w^T + dt_b)   [4096 x 2048], K=64
        dtconv_k<<<(NTOK * DTR) / 256, 256>>>();
        wconv_k<<<(DI * DTR + 255) / 256, 256>>>(dt_w_l, pwh, pwl, DI * DTR);
        mma_gemm<<<dim3(32, 16, 1), 256, SM_TOT>>>(
            pdah, pdal, DTR, pwh, pwl, DTR, 0, pdt, DI, nullptr, nullptr,
            dt_b_l, 0, NTOK, nullptr, nullptr, nullptr, nullptr, 0, DI, DTR, 2);

        // scan
        ssm_scan_k<<<dim3(BATCH, DI / 128), 128>>>(A_log_l, D_l);

        // out: t = y @ out_w^T         [4096 x 1024], K=2048
        wconv_k<<<(DM * DI + 255) / 256, 256>>>(out_w_l, pwh, pwl, DM * DI);
        mma_gemm<<<dim3(32, 8, 1), 256, SM_TOT>>>(
            pyh, pyl, DI, pwh, pwl, DI, 0, pt, DM, nullptr, nullptr,
            nullptr, 0, NTOK, nullptr, nullptr, nullptr, nullptr, 0, DM, DI, 0);

        addln_k<<<NTOK, 256>>>(ln1_g + (size_t)l * DM, ln1_b + (size_t)l * DM);

        // MoE routing
        route_reset_k<<<1, 32>>>();
        gate_k<<<NTOK, 256>>>(gate_w + (size_t)l * NEXP * DM, gate_b + (size_t)l * NEXP);
        route_offsets_k<<<1, 1>>>();
        route_scatter_k<<<NTOK / 256, 256>>>();

        // moe1: h = relu(gather(x) @ w1[e]^T + b1[e]) -> bf16 hi/lo
        wconv_k<<<(NEXP * HEXP * DM + 255) / 256, 256>>>(e_w1_l, pwh, pwl, NEXP * HEXP * DM);
        mma_gemm<<<dim3(32, 8, NEXP), 256, SM_TOT>>>(
            pxh, pxl, DM, pwh, pwl, DM, (size_t)HEXP * DM, nullptr, HEXP, phh, phl,
            e_b1_l, HEXP, 0, pcnt, poff, pperm, nullptr, 1, HEXP, DM, 1);

        // moe2: t = scatter(topw * (h @ w2[e]^T + b2[e]))
        wconv_k<<<(NEXP * DM * HEXP + 255) / 256, 256>>>(e_w2_l, pwh, pwl, NEXP * DM * HEXP);
        mma_gemm<<<dim3(32, 8, NEXP), 256, SM_TOT>>>(
            phh, phl, HEXP, pwh, pwl, HEXP, (size_t)DM * HEXP, pt, DM, nullptr, nullptr,
            e_b2_l, DM, 0, pcnt, poff, pperm, pew, 2, DM, HEXP, 0);

        addln_k<<<NTOK, 256>>>(ln2_g + (size_t)l * DM, ln2_b + (size_t)l * DM);
    }

    cntb_reset_k<<<1, 32>>>();
    rowmask_k<<<NTOK, 256>>>();
    pool_k<<<dim3(BATCH, DM / 256), 256>>>();
    head_k<<<BATCH, 128>>>(fc1_w, fc1_b, fc2_w, fc2_b, out);
}

// round 5
// speedup vs baseline: 1.6303x; 1.0318x over previous
#include <cuda_runtime.h>
#include <cuda_fp16.h>
#include <math.h>
#include <stdint.h>

// ---------------- problem constants ----------------
#define NTOK  4096            // B*L
#define LSEQ  1024
#define BATCH 4
#define DM    1024
#define DI    2048
#define DS    16
#define DTR   64
#define XPD   96              // DTR + 2*DS
#define NEXP  8
#define HEXP  1024

// ---------------- device scratch ----------------
__device__ float g_x [NTOK*DM];
__device__ float g_uz[NTOK*2*DI];
__device__ float g_u [NTOK*DI];
__device__ float g_xp[NTOK*XPD];
__device__ float g_dt[NTOK*DI];
__device__ float g_t [NTOK*DM];
__device__ float g_mask[NTOK];
__device__ float g_pooled[BATCH*DM];
__device__ int   g_eidx[NTOK];
__device__ float g_ew  [NTOK];
__device__ int   g_perm[NTOK];
__device__ int   g_cnt[NEXP], g_off[NEXP], g_fill[NEXP], g_cntb[BATCH];

// fp16 hi/lo split buffers (activations + weights)
__device__ __half g_xh[NTOK*DM],  g_xl[NTOK*DM];
__device__ __half g_uh[NTOK*DI],  g_ul[NTOK*DI];
__device__ __half g_yh[NTOK*DI],  g_yl[NTOK*DI];
__device__ __half g_hh[NTOK*HEXP],g_hl[NTOK*HEXP];
__device__ __half g_dah[NTOK*DTR],g_dal[NTOK*DTR];
__device__ __half g_wh[NEXP*HEXP*DM], g_wl[NEXP*HEXP*DM];

// ---------------- PTX helpers (base ISA only) ----------------
__device__ __forceinline__ uint32_t smem_u32(const void* p) {
    uint32_t a;
    asm("{ .reg .u64 t; cvta.to.shared.u64 t, %1; cvt.u32.u64 %0, t; }" : "=r"(a) : "l"(p));
    return a;
}
__device__ __forceinline__ void ldsm4(uint32_t* r, uint32_t addr) {
    asm volatile("ldmatrix.sync.aligned.m8n8.x4.shared.b16 {%0,%1,%2,%3}, [%4];"
        : "=r"(r[0]), "=r"(r[1]), "=r"(r[2]), "=r"(r[3]) : "r"(addr));
}
__device__ __forceinline__ void mma_f16(float* c, const uint32_t* a, uint32_t b0, uint32_t b1) {
    asm volatile("mma.sync.aligned.m16n8k16.row.col.f32.f16.f16.f32 "
        "{%0,%1,%2,%3}, {%4,%5,%6,%7}, {%8,%9}, {%0,%1,%2,%3};"
        : "+f"(c[0]), "+f"(c[1]), "+f"(c[2]), "+f"(c[3])
        : "r"(a[0]), "r"(a[1]), "r"(a[2]), "r"(a[3]), "r"(b0), "r"(b1));
}
__device__ __forceinline__ void cpa16(uint32_t saddr, const void* g, bool v) {
    int sz = v ? 16 : 0;
    asm volatile("cp.async.cg.shared.global [%0], [%1], 16, %2;"
        :: "r"(saddr), "l"(g), "r"(sz));
}
#define CP_COMMIT() asm volatile("cp.async.commit_group;" ::: "memory")
#define CP_WAIT1()  asm volatile("cp.async.wait_group 1;" ::: "memory")

// smem geometry: K-chunk 64 fp16 = 128B/row, padded to 144B (conflict-free)
#define ROWB   144
#define ATILE  18432              // 128 * 144
#define STAGEB 36864              // A + B tile
#define SM_TOT 110592             // 3 stages

// ============ fp16 mma.sync GEMM: C[M,N] = act(A @ W^T + bias) ============
// 3 K-segments: (Ah,Wh), (Ah,Wl), (Al,Wh) accumulated in fp32. Missing Al*Wl ~ 2^-22.
// mode 0: dense. mode 1: gather A rows via perm (C compact). mode 2: A compact, scatter C via perm w/ rowscale.
__global__ void __launch_bounds__(256, 2)
mma_gemm(const __half* __restrict__ Ah, const __half* __restrict__ Al, int lda,
         const __half* __restrict__ Wh, const __half* __restrict__ Wl, int ldw, size_t wz,
         float* __restrict__ C, int ldc,
         __half* __restrict__ Ch, __half* __restrict__ Cl,
         const float* __restrict__ bias, int bias_z,
         int M_fixed, const int* __restrict__ cntp, const int* __restrict__ offp,
         const int* __restrict__ perm, const float* __restrict__ rowscale,
         int mode, int N, int K, int act)
{
    int e = blockIdx.z;
    int M = cntp ? cntp[e] : M_fixed;
    int base = offp ? offp[e] : 0;
    int m0 = blockIdx.x * 128;
    if (m0 >= M) return;
    int n0 = blockIdx.y * 128;

    extern __shared__ char smem[];
    uint32_t sb = smem_u32(smem);
    int tid = threadIdx.x;

    // ---- copy mapping: stage = 2048 x 16B chunks; thread -> 4 A rows + 4 B rows ----
    int sub = tid & 7;            // which 16B of the 128B row
    int rq = tid >> 3;            // 0..31, rows rq+32*i

    int arowi[4], wrowi[4];
    uint32_t avm = 0, wvm = 0;
#pragma unroll
    for (int i = 0; i < 4; i++) {
        int mm = m0 + rq + 32 * i;
        bool av = mm < M;
        if (av) avm |= 1u << i;
        int ar;
        if (mode == 1)      ar = av ? perm[base + mm] : 0;
        else if (mode == 2) ar = base + (av ? mm : 0);
        else                ar = av ? mm : 0;
        arowi[i] = ar;
        int nr = n0 + rq + 32 * i;
        bool wv = nr < N;
        if (wv) wvm |= 1u << i;
        wrowi[i] = wv ? nr : 0;
    }
    const __half* WhE = Wh + (size_t)e * wz;
    const __half* WlE = Wl + (size_t)e * wz;

    const int NKC = K / 64;
    const int NC = 3 * NKC;

#define COPY_STAGE(c, s) do { \
        int _seg = (c) / NKC; int _k0 = ((c) - _seg * NKC) * 64; \
        const __half* _Ap = (_seg == 2) ? Al : Ah; \
        const __half* _Wp = (_seg == 1) ? WlE : WhE; \
        uint32_t _sB = sb + (uint32_t)(s) * STAGEB + rq * ROWB + sub * 16; \
        _Pragma("unroll") \
        for (int _i = 0; _i < 4; _i++) { \
            cpa16(_sB + _i * (32 * ROWB), \
                  _Ap + (size_t)arowi[_i] * lda + _k0 + sub * 8, (avm >> _i) & 1); \
            cpa16(_sB + _i * (32 * ROWB) + ATILE, \
                  _Wp + (size_t)wrowi[_i] * ldw + _k0 + sub * 8, (wvm >> _i) & 1); \
        } \
    } while (0)

    // ---- mma mapping: 8 warps, warp tile 32x64 (4M x 2N) ----
    int lane = tid & 31;
    int wid = tid >> 5;
    int wm = (wid & 3) * 32;
    int wn = (wid >> 2) * 64;

    int aRow = wm + (lane & 7) + ((lane >> 3) & 1) * 8;
    uint32_t aColB = ((lane >> 4) & 1) * 16;
    int bRow = wn + (lane & 7) + ((lane >> 4) & 1) * 8;
    uint32_t bColB = ((lane >> 3) & 1) * 16;

    float acc[2][8][4] = {};

    COPY_STAGE(0, 0); CP_COMMIT();
    COPY_STAGE(1, 1); CP_COMMIT();

    for (int c = 0; c < NC; c++) {
        CP_WAIT1();
        __syncthreads();
        if (c + 2 < NC) COPY_STAGE(c + 2, (c + 2) % 3);
        CP_COMMIT();

        uint32_t Ab = sb + (uint32_t)(c % 3) * STAGEB;
        uint32_t Bb = Ab + ATILE;
#pragma unroll
        for (int st = 0; st < 4; st++) {
            uint32_t kB = st * 32;
            uint32_t a[2][4], b[4][4];
#pragma unroll
            for (int im = 0; im < 2; im++)
                ldsm4(a[im], Ab + (uint32_t)(aRow + im * 16) * ROWB + kB + aColB);
#pragma unroll
            for (int g = 0; g < 4; g++)
                ldsm4(b[g], Bb + (uint32_t)(bRow + g * 16) * ROWB + kB + bColB);
#pragma unroll
            for (int im = 0; im < 2; im++)
#pragma unroll
                for (int in = 0; in < 8; in++)
                    mma_f16(acc[im][in], a[im], b[in >> 1][(in & 1) * 2], b[in >> 1][(in & 1) * 2 + 1]);
        }
    }

    // ---- epilogue ----
    int lq = lane >> 2;
    int lr = lane & 3;
    const float* bp = bias ? (bias + (size_t)e * bias_z) : nullptr;
#pragma unroll
    for (int im = 0; im < 2; im++) {
#pragma unroll
        for (int r2 = 0; r2 < 2; r2++) {
            int m = m0 + wm + im * 16 + lq + r2 * 8;
            if (m >= M) continue;
            long crow; float scale = 1.f;
            if (mode == 2)      { crow = perm[base + m]; scale = rowscale[crow]; }
            else if (mode == 1) { crow = base + m; }
            else                { crow = m; }
#pragma unroll
            for (int in = 0; in < 8; in++) {
                int n = n0 + wn + in * 8 + lr * 2;
                if (n >= N) continue;
                float v0 = acc[im][in][r2 * 2 + 0];
                float v1 = acc[im][in][r2 * 2 + 1];
                if (bp) { v0 += bp[n]; v1 += bp[n + 1]; }
                if (act == 1) { v0 = fmaxf(v0, 0.f); v1 = fmaxf(v1, 0.f); }
                else if (act == 2) {
                    v0 = (v0 > 20.f) ? v0 : log1pf(__expf(v0));
                    v1 = (v1 > 20.f) ? v1 : log1pf(__expf(v1));
                }
                if (Ch) {
                    __half h0 = __float2half_rn(v0);
                    __half h1 = __float2half_rn(v1);
                    size_t o = (size_t)crow * ldc + n;
                    Ch[o] = h0;     Cl[o]     = __float2half_rn(v0 - __half2float(h0));
                    Ch[o + 1] = h1; Cl[o + 1] = __float2half_rn(v1 - __half2float(h1));
                } else {
                    size_t o = (size_t)crow * ldc + n;
                    C[o] = v0 * scale;
                    C[o + 1] = v1 * scale;
                }
            }
        }
    }
#undef COPY_STAGE
}

// ---------------- fp16 split helpers ----------------
__device__ __forceinline__ void split2(float v, __half& h, __half& l) {
    h = __float2half_rn(v);
    l = __float2half_rn(v - __half2float(h));
}

__global__ void wconv_k(const float* __restrict__ w, __half* __restrict__ h,
                        __half* __restrict__ l, int n) {
    int i = blockIdx.x * 256 + threadIdx.x;
    if (i >= n) return;
    split2(w[i], h[i], l[i]);
}

__global__ void dtconv_k() {  // xp[:, :DTR] -> g_dah/g_dal (compact)
    int i = blockIdx.x * 256 + threadIdx.x;   // NTOK*DTR
    int t = i >> 6, c = i & 63;
    split2(g_xp[t * XPD + c], g_dah[i], g_dal[i]);
}

// ---------------- embed ----------------
__global__ void embed_k(const int* __restrict__ tok, const float* __restrict__ emb,
                        const float* __restrict__ pos) {
    int i = blockIdx.x * blockDim.x + threadIdx.x;
    int t = i / DM, d = i % DM;
    int l = t % LSEQ;
    float v = emb[(size_t)tok[t] * DM + d] + pos[l * DM + d];
    g_x[i] = v;
    split2(v, g_xh[i], g_xl[i]);
}

// ---------------- conv + silu ----------------
__global__ void conv_silu_k(const float* __restrict__ cw, const float* __restrict__ cb) {
    int i = blockIdx.x * 256 + threadIdx.x;
    if (i >= NTOK * DI) return;
    int t = i / DI, d = i % DI;
    int b = t / LSEQ, l = t % LSEQ;
    float acc = cb[d];
#pragma unroll
    for (int k = 0; k < 4; k++) {
        int ll = l - 3 + k;
        if (ll >= 0) acc += g_uz[(size_t)(b * LSEQ + ll) * (2 * DI) + d] * cw[d * 4 + k];
    }
    float v = acc / (1.f + __expf(-acc));
    g_u[i] = v;
    split2(v, g_uh[i], g_ul[i]);
}

// ---------------- selective scan ----------------
__global__ void __launch_bounds__(128) ssm_scan_k(const float* __restrict__ A_log,
                                                  const float* __restrict__ Dp) {
    int b = blockIdx.x;
    int d = blockIdx.y * 128 + threadIdx.x;
    float A[DS];
#pragma unroll
    for (int n = 0; n < DS; n++) A[n] = -expf(A_log[d * DS + n]);
    float Dv = Dp[d];
    float h[DS];
#pragma unroll
    for (int n = 0; n < DS; n++) h[n] = 0.f;

    __shared__ float Bs[64][DS], Cs[64][DS];

    for (int c = 0; c < LSEQ / 64; c++) {
        __syncthreads();
        for (int i = threadIdx.x; i < 64 * DS; i += 128) {
            int s = i / DS, n = i % DS;
            int tok = b * LSEQ + c * 64 + s;
            Bs[s][n] = g_xp[tok * XPD + DTR + n];
            Cs[s][n] = g_xp[tok * XPD + DTR + DS + n];
        }
        __syncthreads();
        for (int s = 0; s < 64; s++) {
            int tok = b * LSEQ + c * 64 + s;
            float ut  = g_u [(size_t)tok * DI + d];
            float dtt = g_dt[(size_t)tok * DI + d];
            float du = dtt * ut;
            float yv = 0.f;
#pragma unroll
            for (int n = 0; n < DS; n++) {
                h[n] = __expf(dtt * A[n]) * h[n] + du * Bs[s][n];
                yv += h[n] * Cs[s][n];
            }
            yv += ut * Dv;
            float z = g_uz[(size_t)tok * (2 * DI) + DI + d];
            float y = yv * (z / (1.f + __expf(-z)));
            size_t o = (size_t)tok * DI + d;
            split2(y, g_yh[o], g_yl[o]);
        }
    }
}

// ---------------- x += LayerNorm(g_t), refresh hi/lo ----------------
__global__ void addln_k(const float* __restrict__ g, const float* __restrict__ bb) {
    int tok = blockIdx.x;
    const float* t = g_t + (size_t)tok * DM;
    float* x = g_x + (size_t)tok * DM;
    int tid = threadIdx.x;
    float v[4]; float s = 0.f;
#pragma unroll
    for (int i = 0; i < 4; i++) { v[i] = t[tid + i * 256]; s += v[i]; }
    __shared__ float sm[256];
    sm[tid] = s; __syncthreads();
    for (int st = 128; st > 0; st >>= 1) { if (tid < st) sm[tid] += sm[tid + st]; __syncthreads(); }
    float mean = sm[0] / DM;
    __syncthreads();
    float q = 0.f;
#pragma unroll
    for (int i = 0; i < 4; i++) { float dd = v[i] - mean; q += dd * dd; }
    sm[tid] = q; __syncthreads();
    for (int st = 128; st > 0; st >>= 1) { if (tid < st) sm[tid] += sm[tid + st]; __syncthreads(); }
    float rstd = rsqrtf(sm[0] / DM + 1e-5f);
#pragma unroll
    for (int i = 0; i < 4; i++) {
        int d = tid + i * 256;
        float nx = x[d] + (v[i] - mean) * rstd * g[d] + bb[d];
        x[d] = nx;
        split2(nx, g_xh[(size_t)tok * DM + d], g_xl[(size_t)tok * DM + d]);
    }
}

// ---------------- MoE gate ----------------
__global__ void gate_k(const float* __restrict__ gw, const float* __restrict__ gb) {
    int tok = blockIdx.x;
    const float* x = g_x + (size_t)tok * DM;
    int tid = threadIdx.x;
    float p[NEXP];
#pragma unroll
    for (int e = 0; e < NEXP; e++) p[e] = 0.f;
    for (int d = tid; d < DM; d += 256) {
        float xv = x[d];
#pragma unroll
        for (int e = 0; e < NEXP; e++) p[e] += xv * gw[e * DM + d];
    }
    __shared__ float sm[NEXP][256];
#pragma unroll
    for (int e = 0; e < NEXP; e++) sm[e][tid] = p[e];
    __syncthreads();
    for (int st = 128; st > 0; st >>= 1) {
        if (tid < st)
#pragma unroll
            for (int e = 0; e < NEXP; e++) sm[e][tid] += sm[e][tid + st];
        __syncthreads();
    }
    if (tid == 0) {
        float m = -1e30f; int bi = 0;
        float lg[NEXP];
#pragma unroll
        for (int e = 0; e < NEXP; e++) {
            lg[e] = sm[e][0] + gb[e];
            if (lg[e] > m) { m = lg[e]; bi = e; }
        }
        float ssum = 0.f;
#pragma unroll
        for (int e = 0; e < NEXP; e++) ssum += __expf(lg[e] - m);
        g_eidx[tok] = bi;
        g_ew[tok] = 1.f / ssum;
        atomicAdd(&g_cnt[bi], 1);
    }
}

__global__ void route_reset_k() { if (threadIdx.x < NEXP) { g_cnt[threadIdx.x] = 0; g_fill[threadIdx.x] = 0; } }
__global__ void route_offsets_k() {
    if (threadIdx.x == 0) { int o = 0; for (int e = 0; e < NEXP; e++) { g_off[e] = o; o += g_cnt[e]; } }
}
__global__ void route_scatter_k() {
    int tok = blockIdx.x * 256 + threadIdx.x;
    if (tok < NTOK) {
        int e = g_eidx[tok];
        int p = g_off[e] + atomicAdd(&g_fill[e], 1);
        g_perm[p] = tok;
    }
}

// ---------------- pooling + head ----------------
__global__ void cntb_reset_k() { if (threadIdx.x < BATCH) g_cntb[threadIdx.x] = 0; }

__global__ void rowmask_k() {
    int tok = blockIdx.x;
    int tid = threadIdx.x;
    float s = 0.f;
#pragma unroll
    for (int i = 0; i < 4; i++) s += g_x[(size_t)tok * DM + tid + i * 256];
    __shared__ float sm[256];
    sm[tid] = s; __syncthreads();
    for (int st = 128; st > 0; st >>= 1) { if (tid < st) sm[tid] += sm[tid + st]; __syncthreads(); }
    if (tid == 0) {
        float m = (sm[0] != 0.f) ? 1.f : 0.f;
        g_mask[tok] = m;
        if (m != 0.f) atomicAdd(&g_cntb[tok / LSEQ], 1);
    }
}

__global__ void pool_k() {
    int b = blockIdx.x;
    int d = blockIdx.y * 256 + threadIdx.x;
    float acc = 0.f;
    for (int l = 0; l < LSEQ; l++)
        acc += g_x[(size_t)(b * LSEQ + l) * DM + d] * g_mask[b * LSEQ + l];
    g_pooled[b * DM + d] = acc / fmaxf((float)g_cntb[b], 1.f);
}

__global__ void head_k(const float* __restrict__ w1, const float* __restrict__ b1,
                       const float* __restrict__ w2, const float* __restrict__ b2,
                       float* __restrict__ out) {
    int b = blockIdx.x;
    int j = threadIdx.x;
    const float* p = g_pooled + b * DM;
    float acc = b1[j];
    for (int k = 0; k < DM; k++) acc += p[k] * w1[j * DM + k];
    __shared__ float h[128];
    h[j] = fmaxf(acc, 0.f);
    __syncthreads();
    if (j < 2) {
        float o = b2[j];
        for (int k = 0; k < 128; k++) o += h[k] * w2[j * 128 + k];
        out[b * 2 + j] = o;
    }
}

// ---------------- launch ----------------
extern "C" void kernel_launch(void* const* d_in, const int* in_sizes, int n_in,
                              void* d_out, int out_size) {
    const int*   tok    = (const int*)  d_in[0];
    const float* emb    = (const float*)d_in[1];
    const float* pos    = (const float*)d_in[2];
    const float* in_w   = (const float*)d_in[3];
    const float* conv_w = (const float*)d_in[4];
    const float* conv_b = (const float*)d_in[5];
    const float* xp_w   = (const float*)d_in[6];
    const float* dt_w   = (const float*)d_in[7];
    const float* dt_b   = (const float*)d_in[8];
    const float* A_log  = (const float*)d_in[9];
    const float* D_ssm  = (const float*)d_in[10];
    const float* out_w  = (const float*)d_in[11];
    const float* ln1_g  = (const float*)d_in[12];
    const float* ln1_b  = (const float*)d_in[13];
    const float* ln2_g  = (const float*)d_in[14];
    const float* ln2_b  = (const float*)d_in[15];
    const float* gate_w = (const float*)d_in[16];
    const float* gate_b = (const float*)d_in[17];
    const float* e_w1   = (const float*)d_in[18];
    const float* e_b1   = (const float*)d_in[19];
    const float* e_w2   = (const float*)d_in[20];
    const float* e_b2   = (const float*)d_in[21];
    const float* fc1_w  = (const float*)d_in[22];
    const float* fc1_b  = (const float*)d_in[23];
    const float* fc2_w  = (const float*)d_in[24];
    const float* fc2_b  = (const float*)d_in[25];
    float* out = (float*)d_out;

    cudaFuncSetAttribute(mma_gemm, cudaFuncAttributeMaxDynamicSharedMemorySize, SM_TOT);

    float *puz, *pxp, *pdt, *pt, *pew;
    __half *pxh, *pxl, *puh, *pul, *pyh, *pyl, *phh, *phl, *pdah, *pdal, *pwh, *pwl;
    int *pcnt, *poff, *pperm;
    cudaGetSymbolAddress((void**)&puz,  g_uz);
    cudaGetSymbolAddress((void**)&pxp,  g_xp);
    cudaGetSymbolAddress((void**)&pdt,  g_dt);
    cudaGetSymbolAddress((void**)&pt,   g_t);
    cudaGetSymbolAddress((void**)&pew,  g_ew);
    cudaGetSymbolAddress((void**)&pxh,  g_xh);
    cudaGetSymbolAddress((void**)&pxl,  g_xl);
    cudaGetSymbolAddress((void**)&puh,  g_uh);
    cudaGetSymbolAddress((void**)&pul,  g_ul);
    cudaGetSymbolAddress((void**)&pyh,  g_yh);
    cudaGetSymbolAddress((void**)&pyl,  g_yl);
    cudaGetSymbolAddress((void**)&phh,  g_hh);
    cudaGetSymbolAddress((void**)&phl,  g_hl);
    cudaGetSymbolAddress((void**)&pdah, g_dah);
    cudaGetSymbolAddress((void**)&pdal, g_dal);
    cudaGetSymbolAddress((void**)&pwh,  g_wh);
    cudaGetSymbolAddress((void**)&pwl,  g_wl);
    cudaGetSymbolAddress((void**)&pcnt, g_cnt);
    cudaGetSymbolAddress((void**)&poff, g_off);
    cudaGetSymbolAddress((void**)&pperm,g_perm);

    embed_k<<<(NTOK * DM) / 256, 256>>>(tok, emb, pos);

    for (int l = 0; l < 2; l++) {
        const float* in_w_l   = in_w   + (size_t)l * (2 * DI) * DM;
        const float* conv_w_l = conv_w + (size_t)l * DI * 4;
        const float* conv_b_l = conv_b + (size_t)l * DI;
        const float* xp_w_l   = xp_w   + (size_t)l * XPD * DI;
        const float* dt_w_l   = dt_w   + (size_t)l * DI * DTR;
        const float* dt_b_l   = dt_b   + (size_t)l * DI;
        const float* A_log_l  = A_log  + (size_t)l * DI * DS;
        const float* D_l      = D_ssm  + (size_t)l * DI;
        const float* out_w_l  = out_w  + (size_t)l * DM * DI;
        const float* e_w1_l   = e_w1   + (size_t)l * NEXP * HEXP * DM;
        const float* e_b1_l   = e_b1   + (size_t)l * NEXP * HEXP;
        const float* e_w2_l   = e_w2   + (size_t)l * NEXP * DM * HEXP;
        const float* e_b2_l   = e_b2   + (size_t)l * NEXP * DM;

        // in_proj: uz = x @ in_w^T     [4096 x 4096], K=1024
        wconv_k<<<(2 * DI * DM + 255) / 256, 256>>>(in_w_l, pwh, pwl, 2 * DI * DM);
        mma_gemm<<<dim3(32, 32, 1), 256, SM_TOT>>>(
            pxh, pxl, DM, pwh, pwl, DM, 0, puz, 2 * DI, nullptr, nullptr,
            nullptr, 0, NTOK, nullptr, nullptr, nullptr, nullptr, 0, 2 * DI, DM, 0);

        conv_silu_k<<<(NTOK * DI) / 256, 256>>>(conv_w_l, conv_b_l);

        // xp = u @ xp_w^T              [4096 x 96], K=2048
        wconv_k<<<(XPD * DI + 255) / 256, 256>>>(xp_w_l, pwh, pwl, XPD * DI);
        mma_gemm<<<dim3(32, 1, 1), 256, SM_TOT>>>(
            puh, pul, DI, pwh, pwl, DI, 0, pxp, XPD, nullptr, nullptr,
            nullptr, 0, NTOK, nullptr, nullptr, nullptr, nullptr, 0, XPD, DI, 0);

        // dt = softplus(xp[:,:64] @ dt_w^T + dt_b)   [4096 x 2048], K=64
        dtconv_k<<<(NTOK * DTR) / 256, 256>>>();
        wconv_k<<<(DI * DTR + 255) / 256, 256>>>(dt_w_l, pwh, pwl, DI * DTR);
        mma_gemm<<<dim3(32, 16, 1), 256, SM_TOT>>>(
            pdah, pdal, DTR, pwh, pwl, DTR, 0, pdt, DI, nullptr, nullptr,
            dt_b_l, 0, NTOK, nullptr, nullptr, nullptr, nullptr, 0, DI, DTR, 2);

        // scan
        ssm_scan_k<<<dim3(BATCH, DI / 128), 128>>>(A_log_l, D_l);

        // out: t = y @ out_w^T         [4096 x 1024], K=2048
        wconv_k<<<(DM * DI + 255) / 256, 256>>>(out_w_l, pwh, pwl, DM * DI);
        mma_gemm<<<dim3(32, 8, 1), 256, SM_TOT>>>(
            pyh, pyl, DI, pwh, pwl, DI, 0, pt, DM, nullptr, nullptr,
            nullptr, 0, NTOK, nullptr, nullptr, nullptr, nullptr, 0, DM, DI, 0);

        addln_k<<<NTOK, 256>>>(ln1_g + (size_t)l * DM, ln1_b + (size_t)l * DM);

        // MoE routing
        route_reset_k<<<1, 32>>>();
        gate_k<<<NTOK, 256>>>(gate_w + (size_t)l * NEXP * DM, gate_b + (size_t)l * NEXP);
        route_offsets_k<<<1, 1>>>();
        route_scatter_k<<<NTOK / 256, 256>>>();

        // moe1: h = relu(gather(x) @ w1[e]^T + b1[e]) -> fp16 hi/lo
        wconv_k<<<(NEXP * HEXP * DM + 255) / 256, 256>>>(e_w1_l, pwh, pwl, NEXP * HEXP * DM);
        mma_gemm<<<dim3(32, 8, NEXP), 256, SM_TOT>>>(
            pxh, pxl, DM, pwh, pwl, DM, (size_t)HEXP * DM, nullptr, HEXP, phh, phl,
            e_b1_l, HEXP, 0, pcnt, poff, pperm, nullptr, 1, HEXP, DM, 1);

        // moe2: t = scatter(topw * (h @ w2[e]^T + b2[e]))
        wconv_k<<<(NEXP * DM * HEXP + 255) / 256, 256>>>(e_w2_l, pwh, pwl, NEXP * DM * HEXP);
        mma_gemm<<<dim3(32, 8, NEXP), 256, SM_TOT>>>(
            phh, phl, HEXP, pwh, pwl, HEXP, (size_t)DM * HEXP, pt, DM, nullptr, nullptr,
            e_b2_l, DM, 0, pcnt, poff, pperm, pew, 2, DM, HEXP, 0);

        addln_k<<<NTOK, 256>>>(ln2_g + (size_t)l * DM, ln2_b + (size_t)l * DM);
    }

    cntb_reset_k<<<1, 32>>>();
    rowmask_k<<<NTOK, 256>>>();
    pool_k<<<dim3(BATCH, DM / 256), 256>>>();
    head_k<<<BATCH, 128>>>(fc1_w, fc1_b, fc2_w, fc2_b, out);
}